// round 6
// baseline (speedup 1.0000x reference)
#include <cuda_runtime.h>
#include <math.h>

// Problem constants
#define B_  8
#define A_  6
#define QS_ 32
#define KS_ 1024
#define C_  256
#define H_  64
#define W_DIM 64
#define NSPAT (C_ * H_ * W_DIM)            // 1048576 per (b, agent)
#define N4 (NSPAT / 4)                     // 262144 float4 per (b, agent)
#define OUT_MAIN ((size_t)B_ * A_ * NSPAT) // 50331648

// Allocation-free scratch (device global)
__device__ float g_attn[B_ * A_ * A_];     // softmaxed attention [B][K][Q]

// --------------------------------------------------------------------------
// Primary kernel: fused attention (scores + softmax). One block per batch,
// 1024 threads. Signals dependent launch immediately (PDL).
// --------------------------------------------------------------------------
__global__ void __launch_bounds__(1024)
attn_fused_kernel(const float* __restrict__ qu,    // [B, A, QS]
                  const float* __restrict__ kmat,  // [B, A, KS]
                  const float* __restrict__ Wm,    // [KS, QS]
                  const float* __restrict__ bias,  // [KS]
                  float* __restrict__ out_tail,    // [B, A, A]
                  int write_tail) {
    asm volatile("griddepcontrol.launch_dependents;");

    const int b    = blockIdx.x;
    const int tid  = threadIdx.x;
    const int warp = tid >> 5;     // 0..31
    const int lane = tid & 31;

    __shared__ float s_k[A_ * KS_];            // 24 KB
    __shared__ float s_part[32][A_][QS_];      // 24 KB
    __shared__ float s_kp[A_][QS_];
    __shared__ float s_kb[A_];
    __shared__ float s_attn[A_ * A_];

    // Stage k[b] cooperatively (1536 float4 -> bulk MLP)
    {
        const float4* __restrict__ kg = (const float4*)(kmat + (size_t)b * A_ * KS_);
        float4* sk4 = (float4*)s_k;
        #pragma unroll
        for (int i = tid; i < A_ * KS_ / 4; i += 1024) sk4[i] = kg[i];
    }
    __syncthreads();

    // Warp w owns d-slice [32w, 32w+32): lane j accumulates kp partials.
    {
        float acc[A_] = {0.f, 0.f, 0.f, 0.f, 0.f, 0.f};
        const int d0 = warp * 32;
        #pragma unroll 8
        for (int i = 0; i < 32; i++) {
            const int d = d0 + i;
            const float wv = Wm[(size_t)d * QS_ + lane];   // coalesced 128B line
            #pragma unroll
            for (int kk = 0; kk < A_; kk++)
                acc[kk] = fmaf(s_k[kk * KS_ + d], wv, acc[kk]);
        }
        #pragma unroll
        for (int kk = 0; kk < A_; kk++)
            s_part[warp][kk][lane] = acc[kk];
    }

    // kb: warps 0..5 each dot(k[kk], bias)
    if (warp < A_) {
        float s = 0.f;
        #pragma unroll 8
        for (int i = 0; i < KS_ / 32; i++) {
            const int d = lane + 32 * i;
            s = fmaf(s_k[warp * KS_ + d], bias[d], s);
        }
        #pragma unroll
        for (int off = 16; off; off >>= 1)
            s += __shfl_down_sync(0xffffffffu, s, off);
        if (lane == 0) s_kb[warp] = s;
    }
    __syncthreads();

    // Reduce 32 warp-partials -> kp[6][32]
    if (tid < A_ * QS_) {
        const int kk = tid >> 5, j = tid & 31;
        float acc = 0.f;
        #pragma unroll
        for (int w = 0; w < 32; w++) acc += s_part[w][kk][j];
        s_kp[kk][j] = acc;
    }
    __syncthreads();

    // scores[kk][qq] = kb[kk] + dot32(kp[kk], qu[b,qq,:])
    if (tid < A_ * A_) {
        const int kk = tid / A_, qq = tid % A_;
        const float* __restrict__ qrow = qu + ((size_t)b * A_ + qq) * QS_;
        float v = s_kb[kk];
        #pragma unroll
        for (int j = 0; j < QS_; j++) v = fmaf(s_kp[kk][j], qrow[j], v);
        s_attn[kk * A_ + qq] = v;
    }
    __syncthreads();

    // softmax over kk for each qq
    if (tid < A_) {
        const int qq = tid;
        float m = -INFINITY;
        #pragma unroll
        for (int kk = 0; kk < A_; kk++) m = fmaxf(m, s_attn[kk * A_ + qq]);
        float e[A_], sum = 0.f;
        #pragma unroll
        for (int kk = 0; kk < A_; kk++) {
            e[kk] = expf(s_attn[kk * A_ + qq] - m);
            sum += e[kk];
        }
        const float inv = 1.f / sum;
        #pragma unroll
        for (int kk = 0; kk < A_; kk++) {
            const float a = e[kk] * inv;
            g_attn[b * 36 + kk * A_ + qq] = a;
            if (write_tail) out_tail[b * 36 + kk * A_ + qq] = a;
        }
    }
}

// --------------------------------------------------------------------------
// Dependent kernel: out[b,q,x] = sum_k attn[b,k,q] * v[b,k,x].
// 2 float4 per thread (x and x+256): block covers a contiguous 8KB chunk,
// 12 loads then 12 stores per thread -> longer read/write bursts, half the
// per-block barrier/index overhead. PDL prologue overlaps the attn kernel.
// --------------------------------------------------------------------------
__global__ void __launch_bounds__(256)
combine_kernel(const float4* __restrict__ v, float4* __restrict__ out) {
    const int b  = blockIdx.y;
    const int x0 = blockIdx.x * 512 + threadIdx.x;   // covers x0 and x0+256

    // Independent prologue: issue all 12 streaming loads (evict-first).
    float4 vv0[A_], vv1[A_];
    #pragma unroll
    for (int kk = 0; kk < A_; kk++) {
        const size_t base = ((size_t)(b * A_ + kk)) * N4;
        vv0[kk] = __ldcs(&v[base + x0]);
        vv1[kk] = __ldcs(&v[base + x0 + 256]);
    }

    // Wait for the attn kernel (completion + memory flush).
    asm volatile("griddepcontrol.wait;" ::: "memory");

    __shared__ float s_a[A_ * A_];
    if (threadIdx.x < A_ * A_) s_a[threadIdx.x] = g_attn[b * 36 + threadIdx.x];
    __syncthreads();

    #pragma unroll
    for (int qq = 0; qq < A_; qq++) {
        float4 o0 = make_float4(0.f, 0.f, 0.f, 0.f);
        float4 o1 = make_float4(0.f, 0.f, 0.f, 0.f);
        #pragma unroll
        for (int kk = 0; kk < A_; kk++) {
            const float a = s_a[kk * A_ + qq];
            o0.x = fmaf(a, vv0[kk].x, o0.x);
            o0.y = fmaf(a, vv0[kk].y, o0.y);
            o0.z = fmaf(a, vv0[kk].z, o0.z);
            o0.w = fmaf(a, vv0[kk].w, o0.w);
            o1.x = fmaf(a, vv1[kk].x, o1.x);
            o1.y = fmaf(a, vv1[kk].y, o1.y);
            o1.z = fmaf(a, vv1[kk].z, o1.z);
            o1.w = fmaf(a, vv1[kk].w, o1.w);
        }
        const size_t base = ((size_t)(b * A_ + qq)) * N4;
        __stcs(&out[base + x0], o0);
        __stcs(&out[base + x0 + 256], o1);
    }
}

extern "C" void kernel_launch(void* const* d_in, const int* in_sizes, int n_in,
                              void* d_out, int out_size) {
    const float* qu   = (const float*)d_in[0];   // [8,6,32]
    const float* kmat = (const float*)d_in[1];   // [8,6,1024]
    const float* v    = (const float*)d_in[2];   // [8,6,256,64,64]
    const float* Wm   = (const float*)d_in[3];   // [1024,32]
    const float* bias = (const float*)d_in[4];   // [1024]

    float* out = (float*)d_out;
    const int write_tail = ((size_t)out_size >= OUT_MAIN + (size_t)B_ * 36) ? 1 : 0;
    float* out_tail = out + OUT_MAIN;

    // Primary: attention (signals dependents early)
    attn_fused_kernel<<<B_, 1024>>>(qu, kmat, Wm, bias, out_tail, write_tail);

    // Dependent: combine with Programmatic Stream Serialization (PDL)
    cudaLaunchConfig_t cfg = {};
    cfg.gridDim  = dim3(N4 / 512, B_, 1);   // 512 x 8 blocks
    cfg.blockDim = dim3(256, 1, 1);
    cfg.dynamicSmemBytes = 0;
    cfg.stream = 0;   // legacy default stream (the one under graph capture)
    cudaLaunchAttribute attr[1];
    attr[0].id = cudaLaunchAttributeProgrammaticStreamSerialization;
    attr[0].val.programmaticStreamSerializationAllowed = 1;
    cfg.attrs = attr;
    cfg.numAttrs = 1;
    cudaLaunchKernelEx(&cfg, combine_kernel, (const float4*)v, (float4*)out);
}